// round 11
// baseline (speedup 1.0000x reference)
#include <cuda_runtime.h>
#include <cuda_fp16.h>
#include <math.h>
#include <stdint.h>

#define N_NODES 50000
#define N_EDGES 320000
#define R_REL   3
#define IN_DIM  768
#define HID     256
#define CAT     768             // R_REL * HID
#define OUT_DIM 64
#define NEG_SLOPE 0.2f
#define NBLK_SCAN 196   // ceil(N_NODES/256)

// ---------------- static scratch (no allocations allowed) ----------------
__device__ __half g_agg[(size_t)N_NODES * CAT];           // per-relation aggregates (75 MB)
__device__ float  g_sq [R_REL * N_NODES];
__device__ float  g_sk [R_REL * N_NODES];
__device__ float  g_qk1[CAT], g_kk1[CAT];                 // W_r q / W_r k, conv1
__device__ float  g_qk2[CAT], g_kk2[CAT];                 // conv2
__device__ __half g_xh [(size_t)N_NODES * IN_DIM];
__device__ __half g_hh [(size_t)N_NODES * HID];
__device__ __half g_wt   [IN_DIM * HID];                  // w_in^T  [256][768]
__device__ __half g_wcat1[HID * CAT];                     // concat conv1 W^T [256][768]
__device__ __half g_wcat2[HID * CAT];                     // concat conv2 W^T [256][768]
__device__ __half g_wot[HID * OUT_DIM];                   // w_out^T [64][256]
// CSR scratch
__device__ int g_deg  [N_NODES];
__device__ int g_excl [N_NODES];
__device__ int g_bsum [256];
__device__ int g_rowptr[N_NODES + 1];
__device__ int g_fill [N_NODES];
__device__ int g_eidx [N_EDGES];        // packed (et<<16)|src, sorted by dst

// ================= baseline-ISA helpers (sm_80+ features only) ============
__device__ __forceinline__ uint32_t smem_u32(const void* p) {
    uint32_t a;
    asm("{ .reg .u64 t; cvta.to.shared.u64 t, %1; cvt.u32.u64 %0, t; }" : "=r"(a) : "l"(p));
    return a;
}
#define CP_ASYNC16(dst, src, sz) \
    asm volatile("cp.async.ca.shared.global [%0], [%1], 16, %2;" \
                 :: "r"(dst), "l"(src), "r"(sz))
#define CP_COMMIT() asm volatile("cp.async.commit_group;")
#define CP_WAIT(n)  asm volatile("cp.async.wait_group %0;" :: "n"(n))

__device__ __forceinline__ void ldsm_x4(uint32_t* r, uint32_t addr) {
    asm volatile("ldmatrix.sync.aligned.m8n8.x4.shared.b16 {%0,%1,%2,%3}, [%4];"
                 : "=r"(r[0]), "=r"(r[1]), "=r"(r[2]), "=r"(r[3]) : "r"(addr));
}
__device__ __forceinline__ void mma16816(float* d, const uint32_t* a,
                                         uint32_t b0, uint32_t b1) {
    asm volatile("mma.sync.aligned.m16n8k16.row.col.f32.f16.f16.f32 "
                 "{%0,%1,%2,%3}, {%4,%5,%6,%7}, {%8,%9}, {%0,%1,%2,%3};"
                 : "+f"(d[0]), "+f"(d[1]), "+f"(d[2]), "+f"(d[3])
                 : "r"(a[0]), "r"(a[1]), "r"(a[2]), "r"(a[3]), "r"(b0), "r"(b1));
}

// ================= HMMA GEMM ==============================================
// MODE 1: bias + relu -> fp16 Ch          (w_in)
// MODE 2: bias + relu + fused classifier -> atomicAdd into Cf (head)
// MODE 3: bias (no relu) -> fp16 Ch       (conv output)
template<int KTOT, int NTOT, int CN, int MODE>
__global__ __launch_bounds__(256, 1)
void gemm_mma(const __half* __restrict__ A, const __half* __restrict__ Bt,
              const float* __restrict__ bias, const float* __restrict__ aux,
              float* __restrict__ Cf, __half* __restrict__ Ch, int M)
{
    constexpr int KT    = KTOT / 64;
    constexpr int LDS   = 72;
    constexpr int A_STG = 128 * LDS * 2;
    constexpr int B_STG = CN * LDS * 2;
    constexpr int A_IT  = 128 * 8 / 256;
    constexpr int B_IT  = CN * 8 / 256;
    constexpr int WNSZ  = CN / 2;
    constexpr int NT    = WNSZ / 8;

    extern __shared__ char smem[];
    const uint32_t sb = smem_u32(smem);
    const int tid = threadIdx.x, wid = tid >> 5, lane = tid & 31;
    const int warp_m = wid & 3, warp_n = wid >> 2;
    const int row0 = blockIdx.x * 128;
    const int col0 = blockIdx.y * CN;

    float acc[2][NT][4];
#pragma unroll
    for (int mt = 0; mt < 2; mt++)
#pragma unroll
        for (int nt = 0; nt < NT; nt++)
#pragma unroll
            for (int j = 0; j < 4; j++) acc[mt][nt][j] = 0.f;

    auto prefetch = [&](int kb) {
        int buf = kb & 1;
        uint32_t abase = sb + buf * A_STG;
#pragma unroll
        for (int i = 0; i < A_IT; i++) {
            int q = tid + i * 256, r = q >> 3, c = q & 7;
            uint32_t dst = abase + (uint32_t)(r * LDS + c * 8) * 2;
            const void* src = A + (size_t)(row0 + r) * KTOT + kb * 64 + c * 8;
            CP_ASYNC16(dst, src, (row0 + r < M) ? 16 : 0);
        }
        uint32_t bbase = sb + 2 * A_STG + buf * B_STG;
#pragma unroll
        for (int i = 0; i < B_IT; i++) {
            int q = tid + i * 256, r = q >> 3, c = q & 7;
            uint32_t dst = bbase + (uint32_t)(r * LDS + c * 8) * 2;
            const void* src = Bt + (size_t)(col0 + r) * KTOT + kb * 64 + c * 8;
            CP_ASYNC16(dst, src, 16);
        }
        CP_COMMIT();
    };

    prefetch(0);
    for (int kb = 0; kb < KT; kb++) {
        if (kb + 1 < KT) { prefetch(kb + 1); CP_WAIT(1); }
        else             { CP_WAIT(0); }
        __syncthreads();

        int buf = kb & 1;
        uint32_t a_lane = sb + buf * A_STG +
            (uint32_t)((warp_m * 32 + (lane & 15)) * LDS + (lane >> 4) * 8) * 2;
        uint32_t b_lane = sb + 2 * A_STG + buf * B_STG +
            (uint32_t)((warp_n * WNSZ + (lane >> 4) * 8 + (lane & 7)) * LDS +
                       ((lane >> 3) & 1) * 8) * 2;
#pragma unroll
        for (int ks = 0; ks < 4; ks++) {
            uint32_t a[2][4];
            ldsm_x4(a[0], a_lane + ks * 32);
            ldsm_x4(a[1], a_lane + 16 * LDS * 2 + ks * 32);
            uint32_t b[NT / 2][4];
#pragma unroll
            for (int n2 = 0; n2 < NT / 2; n2++)
                ldsm_x4(b[n2], b_lane + n2 * 16 * LDS * 2 + ks * 32);
#pragma unroll
            for (int mt = 0; mt < 2; mt++)
#pragma unroll
                for (int nt = 0; nt < NT; nt++)
                    mma16816(acc[mt][nt], a[mt],
                             b[nt >> 1][(nt & 1) * 2], b[nt >> 1][(nt & 1) * 2 + 1]);
        }
        __syncthreads();
    }

    const int r_base = row0 + warp_m * 32 + (lane >> 2);
    const int c_base = col0 + warp_n * WNSZ + (lane & 3) * 2;
#pragma unroll
    for (int mt = 0; mt < 2; mt++) {
#pragma unroll
        for (int h = 0; h < 2; h++) {
            const int gm = r_base + mt * 16 + h * 8;
            if (MODE == 1 || MODE == 3) {
                if (gm < M) {
#pragma unroll
                    for (int nt = 0; nt < NT; nt++) {
                        int c = c_base + nt * 8;
                        float v0 = acc[mt][nt][h * 2 + 0] + __ldg(bias + c);
                        float v1 = acc[mt][nt][h * 2 + 1] + __ldg(bias + c + 1);
                        if (MODE == 1) { v0 = fmaxf(v0, 0.f); v1 = fmaxf(v1, 0.f); }
                        *(__half2*)(Ch + (size_t)gm * NTOT + c) = __floats2half2_rn(v0, v1);
                    }
                }
            } else {  // MODE 2: fused relu + classifier (aux = w_cls [64,2])
                float a0 = 0.f, a1 = 0.f;
#pragma unroll
                for (int nt = 0; nt < NT; nt++) {
                    int c = c_base + nt * 8;
                    float t0 = fmaxf(acc[mt][nt][h * 2 + 0] + __ldg(bias + c), 0.f);
                    float t1 = fmaxf(acc[mt][nt][h * 2 + 1] + __ldg(bias + c + 1), 0.f);
                    a0 = fmaf(t0, __ldg(aux + c * 2),     fmaf(t1, __ldg(aux + (c + 1) * 2),     a0));
                    a1 = fmaf(t0, __ldg(aux + c * 2 + 1), fmaf(t1, __ldg(aux + (c + 1) * 2 + 1), a1));
                }
                a0 += __shfl_xor_sync(0xffffffffu, a0, 1);
                a0 += __shfl_xor_sync(0xffffffffu, a0, 2);
                a1 += __shfl_xor_sync(0xffffffffu, a1, 1);
                a1 += __shfl_xor_sync(0xffffffffu, a1, 2);
                if ((lane & 3) == 0 && gm < M) {
                    atomicAdd(Cf + (size_t)gm * 2 + 0, a0);
                    atomicAdd(Cf + (size_t)gm * 2 + 1, a1);
                }
            }
        }
    }
}

// ---------------- prep kernels --------------------------------------------
__global__ void transpose_wt(const float* __restrict__ in, __half* __restrict__ out,
                             int K, int N)
{
    int o = blockIdx.x * 256 + threadIdx.x;
    if (o >= K * N) return;
    int n = o / K, k = o % K;
    out[o] = __float2half(in[(size_t)k * N + n]);
}

// Wcat^T[o][r*HID + i] = W[r][i][o]  -> [HID][CAT] fp16
__global__ void build_wcat(const float* __restrict__ W, __half* __restrict__ out)
{
    int idx = blockIdx.x * 256 + threadIdx.x;
    if (idx >= R_REL * HID * HID) return;
    int r = idx >> 16, rem = idx & 0xFFFF;
    int i = rem >> 8, o = rem & 255;
    out[(size_t)o * CAT + r * HID + i] = __float2half(W[idx]);
}

// qk[r*HID + i] = sum_o W[r][i][o]*q[o]; kk likewise. One warp per (r,i).
__global__ void qkvec_kernel(const float* __restrict__ W, const float* __restrict__ q,
                             const float* __restrict__ k, float* __restrict__ qk,
                             float* __restrict__ kk)
{
    int w = blockIdx.x * 8 + (threadIdx.x >> 5);
    int lane = threadIdx.x & 31;
    if (w >= R_REL * HID) return;
    const float* row = W + (size_t)w * HID;
    float aq = 0.f, ak = 0.f;
#pragma unroll
    for (int j = 0; j < 8; j++) {
        float v = row[lane * 8 + j];
        aq = fmaf(v, __ldg(q + lane * 8 + j), aq);
        ak = fmaf(v, __ldg(k + lane * 8 + j), ak);
    }
#pragma unroll
    for (int o = 16; o; o >>= 1) {
        aq += __shfl_xor_sync(0xffffffffu, aq, o);
        ak += __shfl_xor_sync(0xffffffffu, ak, o);
    }
    if (lane == 0) { qk[w] = aq; kk[w] = ak; }
}

// sq[r*N+n] = h[n]·qk[r], sk[r*N+n] = h[n]·kk[r].  One warp per node.
__global__ __launch_bounds__(256)
void sqk_kernel(const __half* __restrict__ hh, const float* __restrict__ qk,
                const float* __restrict__ kk, float* __restrict__ sq,
                float* __restrict__ sk)
{
    __shared__ float s_qk[CAT], s_kk[CAT];
    const int tid = threadIdx.x;
    for (int i = tid; i < CAT; i += 256) { s_qk[i] = qk[i]; s_kk[i] = kk[i]; }
    __syncthreads();

    const int n = blockIdx.x * 8 + (tid >> 5);
    const int lane = tid & 31;
    uint4 v = *(const uint4*)(hh + (size_t)n * HID + lane * 8);
    const __half2* hp = (const __half2*)&v;
    float h[8];
#pragma unroll
    for (int j = 0; j < 4; j++) {
        float2 f = __half22float2(hp[j]);
        h[2 * j] = f.x; h[2 * j + 1] = f.y;
    }
    float aq0 = 0.f, ak0 = 0.f, aq1 = 0.f, ak1 = 0.f, aq2 = 0.f, ak2 = 0.f;
#pragma unroll
    for (int j = 0; j < 8; j++) {
        int c = lane * 8 + j;
        aq0 = fmaf(h[j], s_qk[c],           aq0);
        ak0 = fmaf(h[j], s_kk[c],           ak0);
        aq1 = fmaf(h[j], s_qk[HID + c],     aq1);
        ak1 = fmaf(h[j], s_kk[HID + c],     ak1);
        aq2 = fmaf(h[j], s_qk[2 * HID + c], aq2);
        ak2 = fmaf(h[j], s_kk[2 * HID + c], ak2);
    }
#pragma unroll
    for (int o = 16; o; o >>= 1) {
        aq0 += __shfl_xor_sync(0xffffffffu, aq0, o);
        ak0 += __shfl_xor_sync(0xffffffffu, ak0, o);
        aq1 += __shfl_xor_sync(0xffffffffu, aq1, o);
        ak1 += __shfl_xor_sync(0xffffffffu, ak1, o);
        aq2 += __shfl_xor_sync(0xffffffffu, aq2, o);
        ak2 += __shfl_xor_sync(0xffffffffu, ak2, o);
    }
    if (lane == 0) {
        sq[n] = aq0;  sk[n] = ak0;
        sq[N_NODES + n] = aq1;  sk[N_NODES + n] = ak1;
        sq[2 * N_NODES + n] = aq2;  sk[2 * N_NODES + n] = ak2;
    }
}

__global__ void f2h4_kernel(const float4* __restrict__ in, __half2* __restrict__ out,
                            size_t n4)
{
    size_t i = (size_t)blockIdx.x * 256 + threadIdx.x;
    if (i >= n4) return;
    float4 v = in[i];
    out[2 * i]     = __floats2half2_rn(v.x, v.y);
    out[2 * i + 1] = __floats2half2_rn(v.z, v.w);
}

__global__ void out_init(float* __restrict__ out, const float* __restrict__ b_cls)
{
    int i = blockIdx.x * 256 + threadIdx.x;
    if (i < N_NODES * 2) out[i] = b_cls[i & 1];
}

// ---------------- CSR build ------------------------------------------------
__global__ void csr_zero(int* __restrict__ deg)
{
    int i = blockIdx.x * 256 + threadIdx.x;
    if (i < N_NODES) deg[i] = 0;
}
__global__ void csr_hist(const int* __restrict__ dst, int* __restrict__ deg)
{
    int e = blockIdx.x * 256 + threadIdx.x;
    if (e < N_EDGES) atomicAdd(&deg[dst[e]], 1);
}
__global__ void csr_scan1(const int* __restrict__ deg, int* __restrict__ excl,
                          int* __restrict__ bsum)
{
    __shared__ int sm[256];
    int t = threadIdx.x, i = blockIdx.x * 256 + t;
    int v = (i < N_NODES) ? deg[i] : 0;
    sm[t] = v;
    __syncthreads();
    for (int off = 1; off < 256; off <<= 1) {
        int x = (t >= off) ? sm[t - off] : 0;
        __syncthreads();
        if (t >= off) sm[t] += x;
        __syncthreads();
    }
    if (i < N_NODES) excl[i] = sm[t] - v;
    if (t == 255) bsum[blockIdx.x] = sm[255];
}
__global__ void csr_scan2(int* __restrict__ bsum)
{
    __shared__ int sm[256];
    int t = threadIdx.x;
    int v = (t < NBLK_SCAN) ? bsum[t] : 0;
    sm[t] = v;
    __syncthreads();
    for (int off = 1; off < 256; off <<= 1) {
        int x = (t >= off) ? sm[t - off] : 0;
        __syncthreads();
        if (t >= off) sm[t] += x;
        __syncthreads();
    }
    if (t < NBLK_SCAN) bsum[t] = sm[t] - v;
}
__global__ void csr_scan3(const int* __restrict__ excl, const int* __restrict__ bsum,
                          int* __restrict__ rowptr, int* __restrict__ fill)
{
    int i = blockIdx.x * 256 + threadIdx.x;
    if (i < N_NODES) {
        int p = excl[i] + bsum[i >> 8];
        rowptr[i] = p;
        fill[i]   = p;
    }
    if (i == 0) rowptr[N_NODES] = N_EDGES;
}
__global__ void csr_scatter(const int* __restrict__ src, const int* __restrict__ dst,
                            const int* __restrict__ et, int* __restrict__ fill,
                            int* __restrict__ eidx)
{
    int e = blockIdx.x * 256 + threadIdx.x;
    if (e >= N_EDGES) return;
    int pos = atomicAdd(&fill[dst[e]], 1);
    eidx[pos] = src[e] | (et[e] << 16);
}

// ---------------- fused softmax-aggregate (h-space, per relation) ----------
// agg[d, r*HID+:] = (sum_{e in r, dst=d} ea_e * h[s_e, :]) / (sum_all ea + eps)
// Same proven structure as R7/R8 aggregate: per-edge shfl broadcast loop,
// explicit register accumulators, no pointer-indexed locals.
#define ACC8(A, cf, v) do {                                                  \
    const __half2* _hp = (const __half2*)&(v);                               \
    float2 _f0 = __half22float2(_hp[0]);                                     \
    float2 _f1 = __half22float2(_hp[1]);                                     \
    float2 _f2 = __half22float2(_hp[2]);                                     \
    float2 _f3 = __half22float2(_hp[3]);                                     \
    A[0] = fmaf(cf, _f0.x, A[0]); A[1] = fmaf(cf, _f0.y, A[1]);              \
    A[2] = fmaf(cf, _f1.x, A[2]); A[3] = fmaf(cf, _f1.y, A[3]);              \
    A[4] = fmaf(cf, _f2.x, A[4]); A[5] = fmaf(cf, _f2.y, A[5]);              \
    A[6] = fmaf(cf, _f3.x, A[6]); A[7] = fmaf(cf, _f3.y, A[7]);              \
} while (0)

#define STORE8(ptr, A, inv) do {                                             \
    __half2 _h0 = __floats2half2_rn(A[0] * (inv), A[1] * (inv));             \
    __half2 _h1 = __floats2half2_rn(A[2] * (inv), A[3] * (inv));             \
    __half2 _h2 = __floats2half2_rn(A[4] * (inv), A[5] * (inv));             \
    __half2 _h3 = __floats2half2_rn(A[6] * (inv), A[7] * (inv));             \
    *(uint4*)(ptr) = make_uint4(*(uint32_t*)&_h0, *(uint32_t*)&_h1,          \
                                *(uint32_t*)&_h2, *(uint32_t*)&_h3);         \
} while (0)

__global__ __launch_bounds__(256)
void aggregate_h(const int* __restrict__ rowptr, const int* __restrict__ eidx,
                 const float* __restrict__ sq, const float* __restrict__ sk,
                 const __half* __restrict__ hh, __half* __restrict__ agg)
{
    const int d    = blockIdx.x * 8 + (threadIdx.x >> 5);
    const int lane = threadIdx.x & 31;
    const int start = rowptr[d], end = rowptr[d + 1];
    const int deg = end - start;
    const int c0 = lane * 8;

    float a0[8] = {}, a1[8] = {}, a2[8] = {};
    float dn = 0.f;

    if (deg > 0) {
        // pass 1: segment max of leaky_relu scores (strided, bounded)
        float m = -INFINITY;
        for (int i = start + lane; i < end; i += 32) {
            int pk = eidx[i];
            int s = pk & 0xFFFF, r = pk >> 16;
            float a = __ldg(sq + r * N_NODES + d) + __ldg(sk + r * N_NODES + s);
            a = (a > 0.f) ? a : NEG_SLOPE * a;
            m = fmaxf(m, a);
        }
#pragma unroll
        for (int o = 16; o; o >>= 1) m = fmaxf(m, __shfl_xor_sync(0xffffffffu, m, o));

        // pass 2: exp + denom + per-relation accumulate
        for (int base = start; base < end; base += 32) {
            int i = base + lane;
            float ea = 0.f; int pk = 0;
            if (i < end) {
                pk = eidx[i];
                int s = pk & 0xFFFF, r = pk >> 16;
                float a = __ldg(sq + r * N_NODES + d) + __ldg(sk + r * N_NODES + s);
                a = (a > 0.f) ? a : NEG_SLOPE * a;
                ea = __expf(a - m);
            }
            dn += ea;
            int cnt = end - base; if (cnt > 32) cnt = 32;
            for (int l = 0; l < cnt; l++) {
                float cf = __shfl_sync(0xffffffffu, ea, l);
                int pkl  = __shfl_sync(0xffffffffu, pk, l);
                int s = pkl & 0xFFFF, r = pkl >> 16;
                uint4 v = *(const uint4*)(hh + (size_t)s * HID + c0);
                if (r == 0)      { ACC8(a0, cf, v); }
                else if (r == 1) { ACC8(a1, cf, v); }
                else             { ACC8(a2, cf, v); }
            }
        }
#pragma unroll
        for (int o = 16; o; o >>= 1) dn += __shfl_xor_sync(0xffffffffu, dn, o);
    }

    float inv = (deg > 0) ? 1.f / (dn + 1e-16f) : 0.f;
    __half* orow = agg + (size_t)d * CAT;
    STORE8(orow + c0,           a0, inv);
    STORE8(orow + HID + c0,     a1, inv);
    STORE8(orow + 2 * HID + c0, a2, inv);
}

// ---------------- host orchestration --------------------------------------
extern "C" void kernel_launch(void* const* d_in, const int* in_sizes, int n_in,
                              void* d_out, int out_size)
{
    const float* x          = (const float*)d_in[0];
    const int*   edge_index = (const int*)  d_in[1];
    const int*   edge_type  = (const int*)  d_in[2];
    const float* w_in  = (const float*)d_in[3];
    const float* b_in  = (const float*)d_in[4];
    const float* c1w = (const float*)d_in[5];
    const float* c1q = (const float*)d_in[6];
    const float* c1k = (const float*)d_in[7];
    const float* c1b = (const float*)d_in[8];
    const float* c2w = (const float*)d_in[9];
    const float* c2q = (const float*)d_in[10];
    const float* c2k = (const float*)d_in[11];
    const float* c2b = (const float*)d_in[12];
    const float* w_out = (const float*)d_in[13];
    const float* b_out = (const float*)d_in[14];
    const float* w_cls = (const float*)d_in[15];
    const float* b_cls = (const float*)d_in[16];
    float* out = (float*)d_out;

    const int* src = edge_index;
    const int* dst = edge_index + N_EDGES;

    float *p_sq, *p_sk, *p_qk1, *p_kk1, *p_qk2, *p_kk2;
    __half *p_agg, *p_xh, *p_hh, *p_wt, *p_wcat1, *p_wcat2, *p_wot;
    int *p_deg, *p_excl, *p_bsum, *p_rowptr, *p_fill, *p_eidx;
    cudaGetSymbolAddress((void**)&p_agg,   g_agg);
    cudaGetSymbolAddress((void**)&p_sq,    g_sq);
    cudaGetSymbolAddress((void**)&p_sk,    g_sk);
    cudaGetSymbolAddress((void**)&p_qk1,   g_qk1);
    cudaGetSymbolAddress((void**)&p_kk1,   g_kk1);
    cudaGetSymbolAddress((void**)&p_qk2,   g_qk2);
    cudaGetSymbolAddress((void**)&p_kk2,   g_kk2);
    cudaGetSymbolAddress((void**)&p_xh,    g_xh);
    cudaGetSymbolAddress((void**)&p_hh,    g_hh);
    cudaGetSymbolAddress((void**)&p_wt,    g_wt);
    cudaGetSymbolAddress((void**)&p_wcat1, g_wcat1);
    cudaGetSymbolAddress((void**)&p_wcat2, g_wcat2);
    cudaGetSymbolAddress((void**)&p_wot,   g_wot);
    cudaGetSymbolAddress((void**)&p_deg,    g_deg);
    cudaGetSymbolAddress((void**)&p_excl,   g_excl);
    cudaGetSymbolAddress((void**)&p_bsum,   g_bsum);
    cudaGetSymbolAddress((void**)&p_rowptr, g_rowptr);
    cudaGetSymbolAddress((void**)&p_fill,   g_fill);
    cudaGetSymbolAddress((void**)&p_eidx,   g_eidx);

    const int SMEM_BIG   = 73728;
    const int SMEM_SMALL = 55296;
    cudaFuncSetAttribute((const void*)gemm_mma<768, 256, 128, 1>,
                         cudaFuncAttributeMaxDynamicSharedMemorySize, SMEM_BIG);
    cudaFuncSetAttribute((const void*)gemm_mma<768, 256, 128, 3>,
                         cudaFuncAttributeMaxDynamicSharedMemorySize, SMEM_BIG);
    cudaFuncSetAttribute((const void*)gemm_mma<256, 64, 64, 2>,
                         cudaFuncAttributeMaxDynamicSharedMemorySize, SMEM_SMALL);

    const int MB = (N_NODES + 127) / 128;   // 391
    const int EB = (N_EDGES + 255) / 256;   // 1250
    const int NB = (N_NODES + 255) / 256;   // 196
    const int WB = (N_NODES + 7) / 8;       // 6250 (warp-per-node kernels)

    // ---- all serial on stream 0 (no fork-join risk) ----

    // CSR build (shared by both conv layers)
    csr_zero   <<<NB, 256>>>(p_deg);
    csr_hist   <<<EB, 256>>>(dst, p_deg);
    csr_scan1  <<<NB, 256>>>(p_deg, p_excl, p_bsum);
    csr_scan2  <<<1,  256>>>(p_bsum);
    csr_scan3  <<<NB, 256>>>(p_excl, p_bsum, p_rowptr, p_fill);
    csr_scatter<<<EB, 256>>>(src, dst, edge_type, p_fill, p_eidx);

    // weight prep
    build_wcat<<<(R_REL * HID * HID + 255) / 256, 256>>>(c1w, p_wcat1);
    build_wcat<<<(R_REL * HID * HID + 255) / 256, 256>>>(c2w, p_wcat2);
    qkvec_kernel<<<(R_REL * HID + 7) / 8, 256>>>(c1w, c1q, c1k, p_qk1, p_kk1);
    qkvec_kernel<<<(R_REL * HID + 7) / 8, 256>>>(c2w, c2q, c2k, p_qk2, p_kk2);
    transpose_wt<<<(HID * OUT_DIM + 255) / 256, 256>>>(w_out, p_wot, HID, OUT_DIM);
    out_init<<<(N_NODES * 2 + 255) / 256, 256>>>(out, b_cls);

    // h = relu(x @ w_in + b_in) -> fp16
    f2h4_kernel<<<(int)(((size_t)N_NODES * IN_DIM / 4 + 255) / 256), 256>>>(
        (const float4*)x, (__half2*)p_xh, (size_t)N_NODES * IN_DIM / 4);
    transpose_wt<<<(IN_DIM * HID + 255) / 256, 256>>>(w_in, p_wt, IN_DIM, HID);
    gemm_mma<768, 256, 128, 1><<<dim3(MB, 2, 1), 256, SMEM_BIG>>>(
        p_xh, p_wt, b_in, nullptr, nullptr, p_hh, N_NODES);

    // conv1: scores -> aggregate(h-space) -> concat GEMM
    sqk_kernel<<<WB, 256>>>(p_hh, p_qk1, p_kk1, p_sq, p_sk);
    aggregate_h<<<WB, 256>>>(p_rowptr, p_eidx, p_sq, p_sk, p_hh, p_agg);
    gemm_mma<768, 256, 128, 3><<<dim3(MB, 2, 1), 256, SMEM_BIG>>>(
        p_agg, p_wcat1, c1b, nullptr, nullptr, p_hh, N_NODES);

    // conv2
    sqk_kernel<<<WB, 256>>>(p_hh, p_qk2, p_kk2, p_sq, p_sk);
    aggregate_h<<<WB, 256>>>(p_rowptr, p_eidx, p_sq, p_sk, p_hh, p_agg);
    gemm_mma<768, 256, 128, 3><<<dim3(MB, 2, 1), 256, SMEM_BIG>>>(
        p_agg, p_wcat2, c2b, nullptr, nullptr, p_hh, N_NODES);

    // head: out = (relu(h @ w_out + b_out)) @ w_cls + b_cls
    gemm_mma<256, 64, 64, 2><<<dim3(MB, 1, 1), 256, SMEM_SMALL>>>(
        p_hh, p_wot, b_out, w_cls, out, nullptr, N_NODES);
}

// round 16
// speedup vs baseline: 1.2503x; 1.2503x over previous
#include <cuda_runtime.h>
#include <cuda_fp16.h>
#include <math.h>
#include <stdint.h>

#define N_NODES 50000
#define N_EDGES 320000
#define R_REL   3
#define IN_DIM  768
#define HID     256
#define OUT_DIM 64
#define NEG_SLOPE 0.2f
#define NBLK_SCAN 196   // ceil(N_NODES/256)

// ---------------- static scratch (no allocations allowed) ----------------
__device__ __half g_xwh[(size_t)R_REL * N_NODES * HID];   // fp16 per-relation transforms (75 MB)
__device__ float  g_sq [R_REL * N_NODES];
__device__ float  g_sk [R_REL * N_NODES];
__device__ __half g_xh [(size_t)N_NODES * IN_DIM];
__device__ __half g_hh [(size_t)N_NODES * HID];
__device__ __half g_wt [IN_DIM * HID];                  // w_in^T  [256][768]
__device__ __half g_cwt[(size_t)R_REL * HID * HID];     // conv W^T [r][256][256]
__device__ __half g_wot[HID * OUT_DIM];                 // w_out^T [64][256]
// CSR scratch
__device__ int g_deg  [N_NODES];
__device__ int g_excl [N_NODES];
__device__ int g_bsum [256];
__device__ int g_rowptr[N_NODES + 1];
__device__ int g_fill [N_NODES];
__device__ int g_eidx [N_EDGES];        // packed (et<<16)|src, sorted by dst

// ================= baseline-ISA helpers (sm_80+ features only) ============
__device__ __forceinline__ uint32_t smem_u32(const void* p) {
    uint32_t a;
    asm("{ .reg .u64 t; cvta.to.shared.u64 t, %1; cvt.u32.u64 %0, t; }" : "=r"(a) : "l"(p));
    return a;
}
#define CP_ASYNC16(dst, src, sz) \
    asm volatile("cp.async.ca.shared.global [%0], [%1], 16, %2;" \
                 :: "r"(dst), "l"(src), "r"(sz))
#define CP_COMMIT() asm volatile("cp.async.commit_group;")
#define CP_WAIT(n)  asm volatile("cp.async.wait_group %0;" :: "n"(n))

__device__ __forceinline__ void ldsm_x4(uint32_t* r, uint32_t addr) {
    asm volatile("ldmatrix.sync.aligned.m8n8.x4.shared.b16 {%0,%1,%2,%3}, [%4];"
                 : "=r"(r[0]), "=r"(r[1]), "=r"(r[2]), "=r"(r[3]) : "r"(addr));
}
__device__ __forceinline__ void mma16816(float* d, const uint32_t* a,
                                         uint32_t b0, uint32_t b1) {
    asm volatile("mma.sync.aligned.m16n8k16.row.col.f32.f16.f16.f32 "
                 "{%0,%1,%2,%3}, {%4,%5,%6,%7}, {%8,%9}, {%0,%1,%2,%3};"
                 : "+f"(d[0]), "+f"(d[1]), "+f"(d[2]), "+f"(d[3])
                 : "r"(a[0]), "r"(a[1]), "r"(a[2]), "r"(a[3]), "r"(b0), "r"(b1));
}

// ================= HMMA GEMM ==============================================
// MODE 0: conv  — fp16 Ch (= xwh, +z strides), fused sq/sk dots (atomicAdd)
// MODE 1: w_in  — bias + relu -> fp16 Ch
// MODE 2: head  — bias + relu + fused classifier -> atomicAdd into Cf(out)
template<int KTOT, int NTOT, int CN, int MODE>
__global__ __launch_bounds__(256, 2)
void gemm_mma(const __half* __restrict__ A, const __half* __restrict__ Bt,
              const float* __restrict__ bias, const float* __restrict__ qv,
              const float* __restrict__ kv, float* __restrict__ Cf,
              __half* __restrict__ Ch, float* __restrict__ sq,
              float* __restrict__ sk, int M)
{
    constexpr int KT    = KTOT / 64;
    constexpr int LDS   = 72;
    constexpr int A_STG = 128 * LDS * 2;
    constexpr int B_STG = CN * LDS * 2;
    constexpr int A_IT  = 128 * 8 / 256;
    constexpr int B_IT  = CN * 8 / 256;
    constexpr int WNSZ  = CN / 2;
    constexpr int NT    = WNSZ / 8;

    extern __shared__ char smem[];
    const uint32_t sb = smem_u32(smem);
    const int tid = threadIdx.x, wid = tid >> 5, lane = tid & 31;
    const int warp_m = wid & 3, warp_n = wid >> 2;
    const int row0 = blockIdx.x * 128;
    const int col0 = blockIdx.y * CN;
    const int z = blockIdx.z;
    const __half* Btz = Bt + (size_t)z * NTOT * KTOT;
    if (MODE == 0) { Ch += (size_t)z * M * NTOT; sq += (size_t)z * M; sk += (size_t)z * M; }

    float acc[2][NT][4];
#pragma unroll
    for (int mt = 0; mt < 2; mt++)
#pragma unroll
        for (int nt = 0; nt < NT; nt++)
#pragma unroll
            for (int j = 0; j < 4; j++) acc[mt][nt][j] = 0.f;

    auto prefetch = [&](int kb) {
        int buf = kb & 1;
        uint32_t abase = sb + buf * A_STG;
#pragma unroll
        for (int i = 0; i < A_IT; i++) {
            int q = tid + i * 256, r = q >> 3, c = q & 7;
            uint32_t dst = abase + (uint32_t)(r * LDS + c * 8) * 2;
            const void* src = A + (size_t)(row0 + r) * KTOT + kb * 64 + c * 8;
            CP_ASYNC16(dst, src, (row0 + r < M) ? 16 : 0);
        }
        uint32_t bbase = sb + 2 * A_STG + buf * B_STG;
#pragma unroll
        for (int i = 0; i < B_IT; i++) {
            int q = tid + i * 256, r = q >> 3, c = q & 7;
            uint32_t dst = bbase + (uint32_t)(r * LDS + c * 8) * 2;
            const void* src = Btz + (size_t)(col0 + r) * KTOT + kb * 64 + c * 8;
            CP_ASYNC16(dst, src, 16);
        }
        CP_COMMIT();
    };

    prefetch(0);
    for (int kb = 0; kb < KT; kb++) {
        if (kb + 1 < KT) { prefetch(kb + 1); CP_WAIT(1); }
        else             { CP_WAIT(0); }
        __syncthreads();

        int buf = kb & 1;
        uint32_t a_lane = sb + buf * A_STG +
            (uint32_t)((warp_m * 32 + (lane & 15)) * LDS + (lane >> 4) * 8) * 2;
        uint32_t b_lane = sb + 2 * A_STG + buf * B_STG +
            (uint32_t)((warp_n * WNSZ + (lane >> 4) * 8 + (lane & 7)) * LDS +
                       ((lane >> 3) & 1) * 8) * 2;
#pragma unroll
        for (int ks = 0; ks < 4; ks++) {
            uint32_t a[2][4];
            ldsm_x4(a[0], a_lane + ks * 32);
            ldsm_x4(a[1], a_lane + 16 * LDS * 2 + ks * 32);
            uint32_t b[NT / 2][4];
#pragma unroll
            for (int n2 = 0; n2 < NT / 2; n2++)
                ldsm_x4(b[n2], b_lane + n2 * 16 * LDS * 2 + ks * 32);
#pragma unroll
            for (int mt = 0; mt < 2; mt++)
#pragma unroll
                for (int nt = 0; nt < NT; nt++)
                    mma16816(acc[mt][nt], a[mt],
                             b[nt >> 1][(nt & 1) * 2], b[nt >> 1][(nt & 1) * 2 + 1]);
        }
        __syncthreads();
    }

    const int r_base = row0 + warp_m * 32 + (lane >> 2);
    const int c_base = col0 + warp_n * WNSZ + (lane & 3) * 2;
#pragma unroll
    for (int mt = 0; mt < 2; mt++) {
#pragma unroll
        for (int h = 0; h < 2; h++) {
            const int gm = r_base + mt * 16 + h * 8;
            if (MODE == 0) {
                float aq = 0.f, ak = 0.f;
#pragma unroll
                for (int nt = 0; nt < NT; nt++) {
                    int c = c_base + nt * 8;
                    float v0 = acc[mt][nt][h * 2 + 0];
                    float v1 = acc[mt][nt][h * 2 + 1];
                    if (gm < M)
                        *(__half2*)(Ch + (size_t)gm * NTOT + c) = __floats2half2_rn(v0, v1);
                    aq = fmaf(v0, __ldg(qv + c), fmaf(v1, __ldg(qv + c + 1), aq));
                    ak = fmaf(v0, __ldg(kv + c), fmaf(v1, __ldg(kv + c + 1), ak));
                }
                aq += __shfl_xor_sync(0xffffffffu, aq, 1);
                aq += __shfl_xor_sync(0xffffffffu, aq, 2);
                ak += __shfl_xor_sync(0xffffffffu, ak, 1);
                ak += __shfl_xor_sync(0xffffffffu, ak, 2);
                if ((lane & 3) == 0 && gm < M) {
                    atomicAdd(sq + gm, aq);
                    atomicAdd(sk + gm, ak);
                }
            } else if (MODE == 1) {
                if (gm < M) {
#pragma unroll
                    for (int nt = 0; nt < NT; nt++) {
                        int c = c_base + nt * 8;
                        float v0 = fmaxf(acc[mt][nt][h * 2 + 0] + __ldg(bias + c), 0.f);
                        float v1 = fmaxf(acc[mt][nt][h * 2 + 1] + __ldg(bias + c + 1), 0.f);
                        *(__half2*)(Ch + (size_t)gm * NTOT + c) = __floats2half2_rn(v0, v1);
                    }
                }
            } else {  // MODE 2: fused relu + classifier (qv = w_cls [64,2])
                float a0 = 0.f, a1 = 0.f;
#pragma unroll
                for (int nt = 0; nt < NT; nt++) {
                    int c = c_base + nt * 8;
                    float t0 = fmaxf(acc[mt][nt][h * 2 + 0] + __ldg(bias + c), 0.f);
                    float t1 = fmaxf(acc[mt][nt][h * 2 + 1] + __ldg(bias + c + 1), 0.f);
                    a0 = fmaf(t0, __ldg(qv + c * 2),     fmaf(t1, __ldg(qv + (c + 1) * 2),     a0));
                    a1 = fmaf(t0, __ldg(qv + c * 2 + 1), fmaf(t1, __ldg(qv + (c + 1) * 2 + 1), a1));
                }
                a0 += __shfl_xor_sync(0xffffffffu, a0, 1);
                a0 += __shfl_xor_sync(0xffffffffu, a0, 2);
                a1 += __shfl_xor_sync(0xffffffffu, a1, 1);
                a1 += __shfl_xor_sync(0xffffffffu, a1, 2);
                if ((lane & 3) == 0 && gm < M) {
                    atomicAdd(Cf + (size_t)gm * 2 + 0, a0);
                    atomicAdd(Cf + (size_t)gm * 2 + 1, a1);
                }
            }
        }
    }
}

// ---------------- prep kernels --------------------------------------------
__global__ void transpose_wt(const float* __restrict__ in, __half* __restrict__ out,
                             int K, int N)
{
    size_t base = (size_t)blockIdx.z * K * N;
    int o = blockIdx.x * 256 + threadIdx.x;
    if (o >= K * N) return;
    int n = o / K, k = o % K;
    out[base + o] = __float2half(in[base + (size_t)k * N + n]);
}

__global__ void f2h4_kernel(const float4* __restrict__ in, __half2* __restrict__ out,
                            size_t n4)
{
    size_t i = (size_t)blockIdx.x * 256 + threadIdx.x;
    if (i >= n4) return;
    float4 v = in[i];
    out[2 * i]     = __floats2half2_rn(v.x, v.y);
    out[2 * i + 1] = __floats2half2_rn(v.z, v.w);
}

__global__ void zero_sqk(float* __restrict__ sq, float* __restrict__ sk)
{
    int i = blockIdx.x * 256 + threadIdx.x;
    if (i < R_REL * N_NODES) { sq[i] = 0.f; sk[i] = 0.f; }
}

__global__ void out_init(float* __restrict__ out, const float* __restrict__ b_cls)
{
    int i = blockIdx.x * 256 + threadIdx.x;
    if (i < N_NODES * 2) out[i] = b_cls[i & 1];
}

// ---------------- CSR build ------------------------------------------------
__global__ void csr_zero(int* __restrict__ deg)
{
    int i = blockIdx.x * 256 + threadIdx.x;
    if (i < N_NODES) deg[i] = 0;
}
__global__ void csr_hist(const int* __restrict__ dst, int* __restrict__ deg)
{
    int e = blockIdx.x * 256 + threadIdx.x;
    if (e < N_EDGES) atomicAdd(&deg[dst[e]], 1);
}
__global__ void csr_scan1(const int* __restrict__ deg, int* __restrict__ excl,
                          int* __restrict__ bsum)
{
    __shared__ int sm[256];
    int t = threadIdx.x, i = blockIdx.x * 256 + t;
    int v = (i < N_NODES) ? deg[i] : 0;
    sm[t] = v;
    __syncthreads();
    for (int off = 1; off < 256; off <<= 1) {
        int x = (t >= off) ? sm[t - off] : 0;
        __syncthreads();
        if (t >= off) sm[t] += x;
        __syncthreads();
    }
    if (i < N_NODES) excl[i] = sm[t] - v;
    if (t == 255) bsum[blockIdx.x] = sm[255];
}
__global__ void csr_scan2(int* __restrict__ bsum)
{
    __shared__ int sm[256];
    int t = threadIdx.x;
    int v = (t < NBLK_SCAN) ? bsum[t] : 0;
    sm[t] = v;
    __syncthreads();
    for (int off = 1; off < 256; off <<= 1) {
        int x = (t >= off) ? sm[t - off] : 0;
        __syncthreads();
        if (t >= off) sm[t] += x;
        __syncthreads();
    }
    if (t < NBLK_SCAN) bsum[t] = sm[t] - v;
}
__global__ void csr_scan3(const int* __restrict__ excl, const int* __restrict__ bsum,
                          int* __restrict__ rowptr, int* __restrict__ fill)
{
    int i = blockIdx.x * 256 + threadIdx.x;
    if (i < N_NODES) {
        int p = excl[i] + bsum[i >> 8];
        rowptr[i] = p;
        fill[i]   = p;
    }
    if (i == 0) rowptr[N_NODES] = N_EDGES;
}
__global__ void csr_scatter(const int* __restrict__ src, const int* __restrict__ dst,
                            const int* __restrict__ et, int* __restrict__ fill,
                            int* __restrict__ eidx)
{
    int e = blockIdx.x * 256 + threadIdx.x;
    if (e >= N_EDGES) return;
    int pos = atomicAdd(&fill[dst[e]], 1);
    eidx[pos] = src[e] | (et[e] << 16);
}

// ---------------- fused softmax-aggregate: one warp per dst node ----------
// Fast path (deg<=32): single pass. General path: two passes.  (R9-proven)
__global__ __launch_bounds__(256)
void aggregate_kernel(const int* __restrict__ rowptr, const int* __restrict__ eidx,
                      const float* __restrict__ sq, const float* __restrict__ sk,
                      const __half* __restrict__ xwh, const float* __restrict__ bias,
                      __half* __restrict__ out_h)
{
    const int d    = blockIdx.x * 8 + (threadIdx.x >> 5);
    const int lane = threadIdx.x & 31;
    const int start = rowptr[d], end = rowptr[d + 1];
    const int deg = end - start;
    const int c0 = lane * 8;

    float acc[8] = {0.f, 0.f, 0.f, 0.f, 0.f, 0.f, 0.f, 0.f};
    float dn = 0.f;

    auto gather_group = [&](float ea, int pk, int l0, int cnt) {
        int kc = cnt - l0; if (kc > 4) kc = 4;
        float cf[4]; uint4 v[4];
#pragma unroll
        for (int j = 0; j < 4; j++) {
            if (j < kc) {
                cf[j] = __shfl_sync(0xffffffffu, ea, l0 + j);
                int pkl = __shfl_sync(0xffffffffu, pk, l0 + j);
                int s = pkl & 0xFFFF, r = pkl >> 16;
                v[j] = *(const uint4*)(xwh + ((size_t)r * N_NODES + s) * HID + c0);
            }
        }
#pragma unroll
        for (int j = 0; j < 4; j++) {
            if (j < kc) {
                const __half2* hp = (const __half2*)&v[j];
#pragma unroll
                for (int q = 0; q < 4; q++) {
                    float2 f = __half22float2(hp[q]);
                    acc[2 * q]     = fmaf(cf[j], f.x, acc[2 * q]);
                    acc[2 * q + 1] = fmaf(cf[j], f.y, acc[2 * q + 1]);
                }
            }
        }
    };

    if (deg > 0 && deg <= 32) {
        int i = start + lane;
        int pk = 0; float a = -INFINITY;
        if (i < end) {
            pk = eidx[i];
            int s = pk & 0xFFFF, r = pk >> 16;
            a = __ldg(sq + r * N_NODES + d) + __ldg(sk + r * N_NODES + s);
            a = (a > 0.f) ? a : NEG_SLOPE * a;
        }
        float m = a;
#pragma unroll
        for (int o = 16; o; o >>= 1) m = fmaxf(m, __shfl_xor_sync(0xffffffffu, m, o));
        float ea = (i < end) ? __expf(a - m) : 0.f;
        dn = ea;
#pragma unroll
        for (int o = 16; o; o >>= 1) dn += __shfl_xor_sync(0xffffffffu, dn, o);
        for (int l0 = 0; l0 < deg; l0 += 4) gather_group(ea, pk, l0, deg);
    } else if (deg > 32) {
        float m = -INFINITY;
        for (int i = start + lane; i < end; i += 32) {
            int pk = eidx[i];
            int s = pk & 0xFFFF, r = pk >> 16;
            float a = __ldg(sq + r * N_NODES + d) + __ldg(sk + r * N_NODES + s);
            a = (a > 0.f) ? a : NEG_SLOPE * a;
            m = fmaxf(m, a);
        }
#pragma unroll
        for (int o = 16; o; o >>= 1) m = fmaxf(m, __shfl_xor_sync(0xffffffffu, m, o));
        for (int base = start; base < end; base += 32) {
            int i = base + lane;
            float ea = 0.f; int pk = 0;
            if (i < end) {
                pk = eidx[i];
                int s = pk & 0xFFFF, r = pk >> 16;
                float a = __ldg(sq + r * N_NODES + d) + __ldg(sk + r * N_NODES + s);
                a = (a > 0.f) ? a : NEG_SLOPE * a;
                ea = __expf(a - m);
            }
            dn += ea;
            int cnt = end - base; if (cnt > 32) cnt = 32;
            for (int l0 = 0; l0 < cnt; l0 += 4) gather_group(ea, pk, l0, cnt);
        }
#pragma unroll
        for (int o = 16; o; o >>= 1) dn += __shfl_xor_sync(0xffffffffu, dn, o);
    }

    float inv = (deg > 0) ? 1.f / (dn + 1e-16f) : 0.f;
    float4 b0 = *(const float4*)(bias + c0);
    float4 b1 = *(const float4*)(bias + c0 + 4);
    __half2 h0 = __floats2half2_rn(fmaf(acc[0], inv, b0.x), fmaf(acc[1], inv, b0.y));
    __half2 h1 = __floats2half2_rn(fmaf(acc[2], inv, b0.z), fmaf(acc[3], inv, b0.w));
    __half2 h2 = __floats2half2_rn(fmaf(acc[4], inv, b1.x), fmaf(acc[5], inv, b1.y));
    __half2 h3 = __floats2half2_rn(fmaf(acc[6], inv, b1.z), fmaf(acc[7], inv, b1.w));
    *(uint4*)(out_h + (size_t)d * HID + c0) = make_uint4(
        *(uint32_t*)&h0, *(uint32_t*)&h1, *(uint32_t*)&h2, *(uint32_t*)&h3);
}

// ---------------- host orchestration --------------------------------------
extern "C" void kernel_launch(void* const* d_in, const int* in_sizes, int n_in,
                              void* d_out, int out_size)
{
    const float* x          = (const float*)d_in[0];
    const int*   edge_index = (const int*)  d_in[1];
    const int*   edge_type  = (const int*)  d_in[2];
    const float* w_in  = (const float*)d_in[3];
    const float* b_in  = (const float*)d_in[4];
    const float* c1w = (const float*)d_in[5];
    const float* c1q = (const float*)d_in[6];
    const float* c1k = (const float*)d_in[7];
    const float* c1b = (const float*)d_in[8];
    const float* c2w = (const float*)d_in[9];
    const float* c2q = (const float*)d_in[10];
    const float* c2k = (const float*)d_in[11];
    const float* c2b = (const float*)d_in[12];
    const float* w_out = (const float*)d_in[13];
    const float* b_out = (const float*)d_in[14];
    const float* w_cls = (const float*)d_in[15];
    const float* b_cls = (const float*)d_in[16];
    float* out = (float*)d_out;

    const int* src = edge_index;
    const int* dst = edge_index + N_EDGES;

    float *p_sq, *p_sk;
    __half *p_xwh, *p_xh, *p_hh, *p_wt, *p_cwt, *p_wot;
    int *p_deg, *p_excl, *p_bsum, *p_rowptr, *p_fill, *p_eidx;
    cudaGetSymbolAddress((void**)&p_xwh, g_xwh);
    cudaGetSymbolAddress((void**)&p_sq,  g_sq);
    cudaGetSymbolAddress((void**)&p_sk,  g_sk);
    cudaGetSymbolAddress((void**)&p_xh,  g_xh);
    cudaGetSymbolAddress((void**)&p_hh,  g_hh);
    cudaGetSymbolAddress((void**)&p_wt,  g_wt);
    cudaGetSymbolAddress((void**)&p_cwt, g_cwt);
    cudaGetSymbolAddress((void**)&p_wot, g_wot);
    cudaGetSymbolAddress((void**)&p_deg,    g_deg);
    cudaGetSymbolAddress((void**)&p_excl,   g_excl);
    cudaGetSymbolAddress((void**)&p_bsum,   g_bsum);
    cudaGetSymbolAddress((void**)&p_rowptr, g_rowptr);
    cudaGetSymbolAddress((void**)&p_fill,   g_fill);
    cudaGetSymbolAddress((void**)&p_eidx,   g_eidx);

    const int SMEM_BIG   = 73728;
    const int SMEM_SMALL = 55296;
    cudaFuncSetAttribute((const void*)gemm_mma<768, 256, 128, 1>,
                         cudaFuncAttributeMaxDynamicSharedMemorySize, SMEM_BIG);
    cudaFuncSetAttribute((const void*)gemm_mma<256, 256, 128, 0>,
                         cudaFuncAttributeMaxDynamicSharedMemorySize, SMEM_BIG);
    cudaFuncSetAttribute((const void*)gemm_mma<256, 64, 64, 2>,
                         cudaFuncAttributeMaxDynamicSharedMemorySize, SMEM_SMALL);

    const int MB = (N_NODES + 127) / 128;   // 391
    const int EB = (N_EDGES + 255) / 256;   // 1250
    const int NB = (N_NODES + 255) / 256;   // 196

    // ---- all serial on stream 0; ordered so launch #6 = conv1 GEMM (ncu -s 5)

    // (1) x -> fp16
    f2h4_kernel<<<(int)(((size_t)N_NODES * IN_DIM / 4 + 255) / 256), 256>>>(
        (const float4*)x, (__half2*)p_xh, (size_t)N_NODES * IN_DIM / 4);
    // (2) w_in^T
    transpose_wt<<<dim3((IN_DIM * HID + 255) / 256, 1, 1), 256>>>(w_in, p_wt, IN_DIM, HID);
    // (3) h = relu(x @ w_in + b_in) -> fp16
    gemm_mma<768, 256, 128, 1><<<dim3(MB, 2, 1), 256, SMEM_BIG>>>(
        p_xh, p_wt, b_in, nullptr, nullptr, nullptr, p_hh, nullptr, nullptr, N_NODES);
    // (4) conv1 W^T
    transpose_wt<<<dim3((HID * HID + 255) / 256, 1, R_REL), 256>>>(c1w, p_cwt, HID, HID);
    // (5) zero sq/sk
    zero_sqk<<<(R_REL * N_NODES + 255) / 256, 256>>>(p_sq, p_sk);
    // (6) conv1 GEMM (fp16 xw + fused sq/sk)   <- ncu profiles this launch
    gemm_mma<256, 256, 128, 0><<<dim3(MB, 2, R_REL), 256, SMEM_BIG>>>(
        p_hh, p_cwt, nullptr, c1q, c1k, nullptr, p_xwh, p_sq, p_sk, N_NODES);

    // (7-12) CSR build (needed before aggregate1 only)
    csr_zero   <<<NB, 256>>>(p_deg);
    csr_hist   <<<EB, 256>>>(dst, p_deg);
    csr_scan1  <<<NB, 256>>>(p_deg, p_excl, p_bsum);
    csr_scan2  <<<1,  256>>>(p_bsum);
    csr_scan3  <<<NB, 256>>>(p_excl, p_bsum, p_rowptr, p_fill);
    csr_scatter<<<EB, 256>>>(src, dst, edge_type, p_fill, p_eidx);

    // (13) aggregate1 -> fp16 hh
    aggregate_kernel<<<N_NODES / 8, 256>>>(p_rowptr, p_eidx, p_sq, p_sk, p_xwh, c1b, p_hh);

    // conv2
    transpose_wt<<<dim3((HID * HID + 255) / 256, 1, R_REL), 256>>>(c2w, p_cwt, HID, HID);
    zero_sqk<<<(R_REL * N_NODES + 255) / 256, 256>>>(p_sq, p_sk);
    gemm_mma<256, 256, 128, 0><<<dim3(MB, 2, R_REL), 256, SMEM_BIG>>>(
        p_hh, p_cwt, nullptr, c2q, c2k, nullptr, p_xwh, p_sq, p_sk, N_NODES);
    aggregate_kernel<<<N_NODES / 8, 256>>>(p_rowptr, p_eidx, p_sq, p_sk, p_xwh, c2b, p_hh);

    // head: w_out^T (was MISSING in R13-R15 — the rel_err=1.0 bug), then
    // out = (relu(h @ w_out + b_out)) @ w_cls + b_cls (fully fused)
    transpose_wt<<<dim3((HID * OUT_DIM + 255) / 256, 1, 1), 256>>>(w_out, p_wot, HID, OUT_DIM);
    out_init<<<(N_NODES * 2 + 255) / 256, 256>>>(out, b_cls);
    gemm_mma<256, 64, 64, 2><<<dim3(MB, 1, 1), 256, SMEM_SMALL>>>(
        p_hh, p_wot, b_out, w_cls, nullptr, out, nullptr, nullptr, nullptr, N_NODES);
}

// round 17
// speedup vs baseline: 1.2757x; 1.0203x over previous
#include <cuda_runtime.h>
#include <cuda_fp16.h>
#include <math.h>
#include <stdint.h>

#define N_NODES 50000
#define N_EDGES 320000
#define R_REL   3
#define IN_DIM  768
#define HID     256
#define OUT_DIM 64
#define NEG_SLOPE 0.2f
#define NBLK_SCAN 196   // ceil(N_NODES/256)

// ---------------- static scratch (no allocations allowed) ----------------
__device__ __half g_xwh[(size_t)R_REL * N_NODES * HID];   // fp16 per-relation transforms (75 MB)
__device__ float  g_sq [R_REL * N_NODES];
__device__ float  g_sk [R_REL * N_NODES];
__device__ __half g_hh [(size_t)N_NODES * HID];
__device__ __half g_wt [IN_DIM * HID];                  // w_in^T  [256][768]
__device__ __half g_cwt[(size_t)R_REL * HID * HID];     // conv W^T [r][256][256]
__device__ __half g_wot[HID * OUT_DIM];                 // w_out^T [64][256]
// CSR scratch
__device__ int g_deg  [N_NODES];
__device__ int g_excl [N_NODES];
__device__ int g_bsum [256];
__device__ int g_rowptr[N_NODES + 1];
__device__ int g_fill [N_NODES];
__device__ int g_eidx [N_EDGES];        // packed (et<<16)|src, sorted by dst

// ================= baseline-ISA helpers (sm_80+ features only) ============
__device__ __forceinline__ uint32_t smem_u32(const void* p) {
    uint32_t a;
    asm("{ .reg .u64 t; cvta.to.shared.u64 t, %1; cvt.u32.u64 %0, t; }" : "=r"(a) : "l"(p));
    return a;
}
#define CP_ASYNC16(dst, src, sz) \
    asm volatile("cp.async.ca.shared.global [%0], [%1], 16, %2;" \
                 :: "r"(dst), "l"(src), "r"(sz))
#define CP_COMMIT() asm volatile("cp.async.commit_group;")
#define CP_WAIT(n)  asm volatile("cp.async.wait_group %0;" :: "n"(n))

__device__ __forceinline__ void ldsm_x4(uint32_t* r, uint32_t addr) {
    asm volatile("ldmatrix.sync.aligned.m8n8.x4.shared.b16 {%0,%1,%2,%3}, [%4];"
                 : "=r"(r[0]), "=r"(r[1]), "=r"(r[2]), "=r"(r[3]) : "r"(addr));
}
__device__ __forceinline__ void mma16816(float* d, const uint32_t* a,
                                         uint32_t b0, uint32_t b1) {
    asm volatile("mma.sync.aligned.m16n8k16.row.col.f32.f16.f16.f32 "
                 "{%0,%1,%2,%3}, {%4,%5,%6,%7}, {%8,%9}, {%0,%1,%2,%3};"
                 : "+f"(d[0]), "+f"(d[1]), "+f"(d[2]), "+f"(d[3])
                 : "r"(a[0]), "r"(a[1]), "r"(a[2]), "r"(a[3]), "r"(b0), "r"(b1));
}

// ================= HMMA GEMM (fp16 A) =====================================
// MODE 0: conv  — fp16 Ch (= xwh, +z strides), fused sq/sk dots (atomicAdd)
// MODE 2: head  — bias + relu + fused classifier -> atomicAdd into Cf(out)
template<int KTOT, int NTOT, int CN, int MODE>
__global__ __launch_bounds__(256, 2)
void gemm_mma(const __half* __restrict__ A, const __half* __restrict__ Bt,
              const float* __restrict__ bias, const float* __restrict__ qv,
              const float* __restrict__ kv, float* __restrict__ Cf,
              __half* __restrict__ Ch, float* __restrict__ sq,
              float* __restrict__ sk, int M)
{
    constexpr int KT    = KTOT / 64;
    constexpr int LDS   = 72;
    constexpr int A_STG = 128 * LDS * 2;
    constexpr int B_STG = CN * LDS * 2;
    constexpr int A_IT  = 128 * 8 / 256;
    constexpr int B_IT  = CN * 8 / 256;
    constexpr int WNSZ  = CN / 2;
    constexpr int NT    = WNSZ / 8;

    extern __shared__ char smem[];
    const uint32_t sb = smem_u32(smem);
    const int tid = threadIdx.x, wid = tid >> 5, lane = tid & 31;
    const int warp_m = wid & 3, warp_n = wid >> 2;
    const int row0 = blockIdx.x * 128;
    const int col0 = blockIdx.y * CN;
    const int z = blockIdx.z;
    const __half* Btz = Bt + (size_t)z * NTOT * KTOT;
    if (MODE == 0) { Ch += (size_t)z * M * NTOT; sq += (size_t)z * M; sk += (size_t)z * M; }

    float acc[2][NT][4];
#pragma unroll
    for (int mt = 0; mt < 2; mt++)
#pragma unroll
        for (int nt = 0; nt < NT; nt++)
#pragma unroll
            for (int j = 0; j < 4; j++) acc[mt][nt][j] = 0.f;

    auto prefetch = [&](int kb) {
        int buf = kb & 1;
        uint32_t abase = sb + buf * A_STG;
#pragma unroll
        for (int i = 0; i < A_IT; i++) {
            int q = tid + i * 256, r = q >> 3, c = q & 7;
            uint32_t dst = abase + (uint32_t)(r * LDS + c * 8) * 2;
            const void* src = A + (size_t)(row0 + r) * KTOT + kb * 64 + c * 8;
            CP_ASYNC16(dst, src, (row0 + r < M) ? 16 : 0);
        }
        uint32_t bbase = sb + 2 * A_STG + buf * B_STG;
#pragma unroll
        for (int i = 0; i < B_IT; i++) {
            int q = tid + i * 256, r = q >> 3, c = q & 7;
            uint32_t dst = bbase + (uint32_t)(r * LDS + c * 8) * 2;
            const void* src = Btz + (size_t)(col0 + r) * KTOT + kb * 64 + c * 8;
            CP_ASYNC16(dst, src, 16);
        }
        CP_COMMIT();
    };

    prefetch(0);
    for (int kb = 0; kb < KT; kb++) {
        if (kb + 1 < KT) { prefetch(kb + 1); CP_WAIT(1); }
        else             { CP_WAIT(0); }
        __syncthreads();

        int buf = kb & 1;
        uint32_t a_lane = sb + buf * A_STG +
            (uint32_t)((warp_m * 32 + (lane & 15)) * LDS + (lane >> 4) * 8) * 2;
        uint32_t b_lane = sb + 2 * A_STG + buf * B_STG +
            (uint32_t)((warp_n * WNSZ + (lane >> 4) * 8 + (lane & 7)) * LDS +
                       ((lane >> 3) & 1) * 8) * 2;
#pragma unroll
        for (int ks = 0; ks < 4; ks++) {
            uint32_t a[2][4];
            ldsm_x4(a[0], a_lane + ks * 32);
            ldsm_x4(a[1], a_lane + 16 * LDS * 2 + ks * 32);
            uint32_t b[NT / 2][4];
#pragma unroll
            for (int n2 = 0; n2 < NT / 2; n2++)
                ldsm_x4(b[n2], b_lane + n2 * 16 * LDS * 2 + ks * 32);
#pragma unroll
            for (int mt = 0; mt < 2; mt++)
#pragma unroll
                for (int nt = 0; nt < NT; nt++)
                    mma16816(acc[mt][nt], a[mt],
                             b[nt >> 1][(nt & 1) * 2], b[nt >> 1][(nt & 1) * 2 + 1]);
        }
        __syncthreads();
    }

    const int r_base = row0 + warp_m * 32 + (lane >> 2);
    const int c_base = col0 + warp_n * WNSZ + (lane & 3) * 2;
#pragma unroll
    for (int mt = 0; mt < 2; mt++) {
#pragma unroll
        for (int h = 0; h < 2; h++) {
            const int gm = r_base + mt * 16 + h * 8;
            if (MODE == 0) {
                float aq = 0.f, ak = 0.f;
#pragma unroll
                for (int nt = 0; nt < NT; nt++) {
                    int c = c_base + nt * 8;
                    float v0 = acc[mt][nt][h * 2 + 0];
                    float v1 = acc[mt][nt][h * 2 + 1];
                    if (gm < M)
                        *(__half2*)(Ch + (size_t)gm * NTOT + c) = __floats2half2_rn(v0, v1);
                    aq = fmaf(v0, __ldg(qv + c), fmaf(v1, __ldg(qv + c + 1), aq));
                    ak = fmaf(v0, __ldg(kv + c), fmaf(v1, __ldg(kv + c + 1), ak));
                }
                aq += __shfl_xor_sync(0xffffffffu, aq, 1);
                aq += __shfl_xor_sync(0xffffffffu, aq, 2);
                ak += __shfl_xor_sync(0xffffffffu, ak, 1);
                ak += __shfl_xor_sync(0xffffffffu, ak, 2);
                if ((lane & 3) == 0 && gm < M) {
                    atomicAdd(sq + gm, aq);
                    atomicAdd(sk + gm, ak);
                }
            } else {  // MODE 2: fused relu + classifier (qv = w_cls [64,2])
                float a0 = 0.f, a1 = 0.f;
#pragma unroll
                for (int nt = 0; nt < NT; nt++) {
                    int c = c_base + nt * 8;
                    float t0 = fmaxf(acc[mt][nt][h * 2 + 0] + __ldg(bias + c), 0.f);
                    float t1 = fmaxf(acc[mt][nt][h * 2 + 1] + __ldg(bias + c + 1), 0.f);
                    a0 = fmaf(t0, __ldg(qv + c * 2),     fmaf(t1, __ldg(qv + (c + 1) * 2),     a0));
                    a1 = fmaf(t0, __ldg(qv + c * 2 + 1), fmaf(t1, __ldg(qv + (c + 1) * 2 + 1), a1));
                }
                a0 += __shfl_xor_sync(0xffffffffu, a0, 1);
                a0 += __shfl_xor_sync(0xffffffffu, a0, 2);
                a1 += __shfl_xor_sync(0xffffffffu, a1, 1);
                a1 += __shfl_xor_sync(0xffffffffu, a1, 2);
                if ((lane & 3) == 0 && gm < M) {
                    atomicAdd(Cf + (size_t)gm * 2 + 0, a0);
                    atomicAdd(Cf + (size_t)gm * 2 + 1, a1);
                }
            }
        }
    }
}

// ================= HMMA GEMM, fp32 A with fused conversion ===============
// w_in layer: Ch = fp16(relu(A32[M,768] @ Bt^T + bias)).  A loaded fp32 via
// register staging (overlaps next tile's loads with current MMA), converted
// to fp16 on the smem store.  B via cp.async.  (256,1): staging needs regs.
__global__ __launch_bounds__(256, 1)
void gemm_f32a(const float* __restrict__ A32, const __half* __restrict__ Bt,
               const float* __restrict__ bias, __half* __restrict__ Ch, int M)
{
    constexpr int KTOT = IN_DIM, CN = 128, KT = KTOT / 64;
    constexpr int LDS   = 72;
    constexpr int A_STG = 128 * LDS * 2;
    constexpr int B_STG = CN * LDS * 2;
    constexpr int A_IT  = 4;
    constexpr int B_IT  = 4;
    constexpr int WNSZ  = CN / 2;
    constexpr int NT    = WNSZ / 8;   // 8

    extern __shared__ char smem[];
    const uint32_t sb = smem_u32(smem);
    const int tid = threadIdx.x, wid = tid >> 5, lane = tid & 31;
    const int warp_m = wid & 3, warp_n = wid >> 2;
    const int row0 = blockIdx.x * 128;
    const int col0 = blockIdx.y * CN;

    float acc[2][NT][4];
#pragma unroll
    for (int mt = 0; mt < 2; mt++)
#pragma unroll
        for (int nt = 0; nt < NT; nt++)
#pragma unroll
            for (int j = 0; j < 4; j++) acc[mt][nt][j] = 0.f;

    float4 ra[A_IT][2];                      // fp32 staging: 8 floats per chunk
    auto load_a = [&](int kb) {
#pragma unroll
        for (int i = 0; i < A_IT; i++) {
            int q = tid + i * 256, r = q >> 3, c = q & 7;
            if (row0 + r < M) {
                const float* p = A32 + (size_t)(row0 + r) * KTOT + kb * 64 + c * 8;
                ra[i][0] = *(const float4*)p;
                ra[i][1] = *(const float4*)(p + 4);
            } else {
                ra[i][0] = make_float4(0.f, 0.f, 0.f, 0.f);
                ra[i][1] = make_float4(0.f, 0.f, 0.f, 0.f);
            }
        }
    };
    auto store_a = [&](int buf) {
        uint32_t abase = sb + buf * A_STG;
#pragma unroll
        for (int i = 0; i < A_IT; i++) {
            int q = tid + i * 256, r = q >> 3, c = q & 7;
            __half2 h0 = __floats2half2_rn(ra[i][0].x, ra[i][0].y);
            __half2 h1 = __floats2half2_rn(ra[i][0].z, ra[i][0].w);
            __half2 h2 = __floats2half2_rn(ra[i][1].x, ra[i][1].y);
            __half2 h3 = __floats2half2_rn(ra[i][1].z, ra[i][1].w);
            *(uint4*)(smem + buf * A_STG + (r * LDS + c * 8) * 2) = make_uint4(
                *(uint32_t*)&h0, *(uint32_t*)&h1, *(uint32_t*)&h2, *(uint32_t*)&h3);
        }
        (void)abase;
    };
    auto prefetch_b = [&](int kb) {
        int buf = kb & 1;
        uint32_t bbase = sb + 2 * A_STG + buf * B_STG;
#pragma unroll
        for (int i = 0; i < B_IT; i++) {
            int q = tid + i * 256, r = q >> 3, c = q & 7;
            uint32_t dst = bbase + (uint32_t)(r * LDS + c * 8) * 2;
            const void* src = Bt + (size_t)(col0 + r) * KTOT + kb * 64 + c * 8;
            CP_ASYNC16(dst, src, 16);
        }
        CP_COMMIT();
    };

    prefetch_b(0);
    load_a(0);
    for (int kb = 0; kb < KT; kb++) {
        int buf = kb & 1;
        store_a(buf);
        if (kb + 1 < KT) { prefetch_b(kb + 1); CP_WAIT(1); }
        else             { CP_WAIT(0); }
        __syncthreads();
        if (kb + 1 < KT) load_a(kb + 1);   // overlap next A loads with MMA

        uint32_t a_lane = sb + buf * A_STG +
            (uint32_t)((warp_m * 32 + (lane & 15)) * LDS + (lane >> 4) * 8) * 2;
        uint32_t b_lane = sb + 2 * A_STG + buf * B_STG +
            (uint32_t)((warp_n * WNSZ + (lane >> 4) * 8 + (lane & 7)) * LDS +
                       ((lane >> 3) & 1) * 8) * 2;
#pragma unroll
        for (int ks = 0; ks < 4; ks++) {
            uint32_t a[2][4];
            ldsm_x4(a[0], a_lane + ks * 32);
            ldsm_x4(a[1], a_lane + 16 * LDS * 2 + ks * 32);
            uint32_t b[NT / 2][4];
#pragma unroll
            for (int n2 = 0; n2 < NT / 2; n2++)
                ldsm_x4(b[n2], b_lane + n2 * 16 * LDS * 2 + ks * 32);
#pragma unroll
            for (int mt = 0; mt < 2; mt++)
#pragma unroll
                for (int nt = 0; nt < NT; nt++)
                    mma16816(acc[mt][nt], a[mt],
                             b[nt >> 1][(nt & 1) * 2], b[nt >> 1][(nt & 1) * 2 + 1]);
        }
        __syncthreads();
    }

    const int r_base = row0 + warp_m * 32 + (lane >> 2);
    const int c_base = col0 + warp_n * WNSZ + (lane & 3) * 2;
#pragma unroll
    for (int mt = 0; mt < 2; mt++) {
#pragma unroll
        for (int h = 0; h < 2; h++) {
            const int gm = r_base + mt * 16 + h * 8;
            if (gm < M) {
#pragma unroll
                for (int nt = 0; nt < NT; nt++) {
                    int c = c_base + nt * 8;
                    float v0 = fmaxf(acc[mt][nt][h * 2 + 0] + __ldg(bias + c), 0.f);
                    float v1 = fmaxf(acc[mt][nt][h * 2 + 1] + __ldg(bias + c + 1), 0.f);
                    *(__half2*)(Ch + (size_t)gm * HID + c) = __floats2half2_rn(v0, v1);
                }
            }
        }
    }
}

// ---------------- prep kernels --------------------------------------------
__global__ void transpose_wt(const float* __restrict__ in, __half* __restrict__ out,
                             int K, int N)
{
    size_t base = (size_t)blockIdx.z * K * N;
    int o = blockIdx.x * 256 + threadIdx.x;
    if (o >= K * N) return;
    int n = o / K, k = o % K;
    out[base + o] = __float2half(in[base + (size_t)k * N + n]);
}

__global__ void zero_sqk(float* __restrict__ sq, float* __restrict__ sk)
{
    int i = blockIdx.x * 256 + threadIdx.x;
    if (i < R_REL * N_NODES) { sq[i] = 0.f; sk[i] = 0.f; }
}

__global__ void out_init(float* __restrict__ out, const float* __restrict__ b_cls)
{
    int i = blockIdx.x * 256 + threadIdx.x;
    if (i < N_NODES * 2) out[i] = b_cls[i & 1];
}

// ---------------- CSR build ------------------------------------------------
__global__ void csr_zero(int* __restrict__ deg)
{
    int i = blockIdx.x * 256 + threadIdx.x;
    if (i < N_NODES) deg[i] = 0;
}
__global__ void csr_hist(const int* __restrict__ dst, int* __restrict__ deg)
{
    int e = blockIdx.x * 256 + threadIdx.x;
    if (e < N_EDGES) atomicAdd(&deg[dst[e]], 1);
}
__global__ void csr_scan1(const int* __restrict__ deg, int* __restrict__ excl,
                          int* __restrict__ bsum)
{
    __shared__ int sm[256];
    int t = threadIdx.x, i = blockIdx.x * 256 + t;
    int v = (i < N_NODES) ? deg[i] : 0;
    sm[t] = v;
    __syncthreads();
    for (int off = 1; off < 256; off <<= 1) {
        int x = (t >= off) ? sm[t - off] : 0;
        __syncthreads();
        if (t >= off) sm[t] += x;
        __syncthreads();
    }
    if (i < N_NODES) excl[i] = sm[t] - v;
    if (t == 255) bsum[blockIdx.x] = sm[255];
}
__global__ void csr_scan2(int* __restrict__ bsum)
{
    __shared__ int sm[256];
    int t = threadIdx.x;
    int v = (t < NBLK_SCAN) ? bsum[t] : 0;
    sm[t] = v;
    __syncthreads();
    for (int off = 1; off < 256; off <<= 1) {
        int x = (t >= off) ? sm[t - off] : 0;
        __syncthreads();
        if (t >= off) sm[t] += x;
        __syncthreads();
    }
    if (t < NBLK_SCAN) bsum[t] = sm[t] - v;
}
__global__ void csr_scan3(const int* __restrict__ excl, const int* __restrict__ bsum,
                          int* __restrict__ rowptr, int* __restrict__ fill)
{
    int i = blockIdx.x * 256 + threadIdx.x;
    if (i < N_NODES) {
        int p = excl[i] + bsum[i >> 8];
        rowptr[i] = p;
        fill[i]   = p;
    }
    if (i == 0) rowptr[N_NODES] = N_EDGES;
}
__global__ void csr_scatter(const int* __restrict__ src, const int* __restrict__ dst,
                            const int* __restrict__ et, int* __restrict__ fill,
                            int* __restrict__ eidx)
{
    int e = blockIdx.x * 256 + threadIdx.x;
    if (e >= N_EDGES) return;
    int pos = atomicAdd(&fill[dst[e]], 1);
    eidx[pos] = src[e] | (et[e] << 16);
}

// ---------------- fused softmax-aggregate: one warp per dst node ----------
__global__ __launch_bounds__(256)
void aggregate_kernel(const int* __restrict__ rowptr, const int* __restrict__ eidx,
                      const float* __restrict__ sq, const float* __restrict__ sk,
                      const __half* __restrict__ xwh, const float* __restrict__ bias,
                      __half* __restrict__ out_h)
{
    const int d    = blockIdx.x * 8 + (threadIdx.x >> 5);
    const int lane = threadIdx.x & 31;
    const int start = rowptr[d], end = rowptr[d + 1];
    const int deg = end - start;
    const int c0 = lane * 8;

    float acc[8] = {0.f, 0.f, 0.f, 0.f, 0.f, 0.f, 0.f, 0.f};
    float dn = 0.f;

    auto gather_group = [&](float ea, int pk, int l0, int cnt) {
        int kc = cnt - l0; if (kc > 4) kc = 4;
        float cf[4]; uint4 v[4];
#pragma unroll
        for (int j = 0; j < 4; j++) {
            if (j < kc) {
                cf[j] = __shfl_sync(0xffffffffu, ea, l0 + j);
                int pkl = __shfl_sync(0xffffffffu, pk, l0 + j);
                int s = pkl & 0xFFFF, r = pkl >> 16;
                v[j] = *(const uint4*)(xwh + ((size_t)r * N_NODES + s) * HID + c0);
            }
        }
#pragma unroll
        for (int j = 0; j < 4; j++) {
            if (j < kc) {
                const __half2* hp = (const __half2*)&v[j];
#pragma unroll
                for (int q = 0; q < 4; q++) {
                    float2 f = __half22float2(hp[q]);
                    acc[2 * q]     = fmaf(cf[j], f.x, acc[2 * q]);
                    acc[2 * q + 1] = fmaf(cf[j], f.y, acc[2 * q + 1]);
                }
            }
        }
    };

    if (deg > 0 && deg <= 32) {
        int i = start + lane;
        int pk = 0; float a = -INFINITY;
        if (i < end) {
            pk = eidx[i];
            int s = pk & 0xFFFF, r = pk >> 16;
            a = __ldg(sq + r * N_NODES + d) + __ldg(sk + r * N_NODES + s);
            a = (a > 0.f) ? a : NEG_SLOPE * a;
        }
        float m = a;
#pragma unroll
        for (int o = 16; o; o >>= 1) m = fmaxf(m, __shfl_xor_sync(0xffffffffu, m, o));
        float ea = (i < end) ? __expf(a - m) : 0.f;
        dn = ea;
#pragma unroll
        for (int o = 16; o; o >>= 1) dn += __shfl_xor_sync(0xffffffffu, dn, o);
        for (int l0 = 0; l0 < deg; l0 += 4) gather_group(ea, pk, l0, deg);
    } else if (deg > 32) {
        float m = -INFINITY;
        for (int i = start + lane; i < end; i += 32) {
            int pk = eidx[i];
            int s = pk & 0xFFFF, r = pk >> 16;
            float a = __ldg(sq + r * N_NODES + d) + __ldg(sk + r * N_NODES + s);
            a = (a > 0.f) ? a : NEG_SLOPE * a;
            m = fmaxf(m, a);
        }
#pragma unroll
        for (int o = 16; o; o >>= 1) m = fmaxf(m, __shfl_xor_sync(0xffffffffu, m, o));
        for (int base = start; base < end; base += 32) {
            int i = base + lane;
            float ea = 0.f; int pk = 0;
            if (i < end) {
                pk = eidx[i];
                int s = pk & 0xFFFF, r = pk >> 16;
                float a = __ldg(sq + r * N_NODES + d) + __ldg(sk + r * N_NODES + s);
                a = (a > 0.f) ? a : NEG_SLOPE * a;
                ea = __expf(a - m);
            }
            dn += ea;
            int cnt = end - base; if (cnt > 32) cnt = 32;
            for (int l0 = 0; l0 < cnt; l0 += 4) gather_group(ea, pk, l0, cnt);
        }
#pragma unroll
        for (int o = 16; o; o >>= 1) dn += __shfl_xor_sync(0xffffffffu, dn, o);
    }

    float inv = (deg > 0) ? 1.f / (dn + 1e-16f) : 0.f;
    float4 b0 = *(const float4*)(bias + c0);
    float4 b1 = *(const float4*)(bias + c0 + 4);
    __half2 h0 = __floats2half2_rn(fmaf(acc[0], inv, b0.x), fmaf(acc[1], inv, b0.y));
    __half2 h1 = __floats2half2_rn(fmaf(acc[2], inv, b0.z), fmaf(acc[3], inv, b0.w));
    __half2 h2 = __floats2half2_rn(fmaf(acc[4], inv, b1.x), fmaf(acc[5], inv, b1.y));
    __half2 h3 = __floats2half2_rn(fmaf(acc[6], inv, b1.z), fmaf(acc[7], inv, b1.w));
    *(uint4*)(out_h + (size_t)d * HID + c0) = make_uint4(
        *(uint32_t*)&h0, *(uint32_t*)&h1, *(uint32_t*)&h2, *(uint32_t*)&h3);
}

// ---------------- host orchestration --------------------------------------
extern "C" void kernel_launch(void* const* d_in, const int* in_sizes, int n_in,
                              void* d_out, int out_size)
{
    const float* x          = (const float*)d_in[0];
    const int*   edge_index = (const int*)  d_in[1];
    const int*   edge_type  = (const int*)  d_in[2];
    const float* w_in  = (const float*)d_in[3];
    const float* b_in  = (const float*)d_in[4];
    const float* c1w = (const float*)d_in[5];
    const float* c1q = (const float*)d_in[6];
    const float* c1k = (const float*)d_in[7];
    const float* c1b = (const float*)d_in[8];
    const float* c2w = (const float*)d_in[9];
    const float* c2q = (const float*)d_in[10];
    const float* c2k = (const float*)d_in[11];
    const float* c2b = (const float*)d_in[12];
    const float* w_out = (const float*)d_in[13];
    const float* b_out = (const float*)d_in[14];
    const float* w_cls = (const float*)d_in[15];
    const float* b_cls = (const float*)d_in[16];
    float* out = (float*)d_out;

    const int* src = edge_index;
    const int* dst = edge_index + N_EDGES;

    float *p_sq, *p_sk;
    __half *p_xwh, *p_hh, *p_wt, *p_cwt, *p_wot;
    int *p_deg, *p_excl, *p_bsum, *p_rowptr, *p_fill, *p_eidx;
    cudaGetSymbolAddress((void**)&p_xwh, g_xwh);
    cudaGetSymbolAddress((void**)&p_sq,  g_sq);
    cudaGetSymbolAddress((void**)&p_sk,  g_sk);
    cudaGetSymbolAddress((void**)&p_hh,  g_hh);
    cudaGetSymbolAddress((void**)&p_wt,  g_wt);
    cudaGetSymbolAddress((void**)&p_cwt, g_cwt);
    cudaGetSymbolAddress((void**)&p_wot, g_wot);
    cudaGetSymbolAddress((void**)&p_deg,    g_deg);
    cudaGetSymbolAddress((void**)&p_excl,   g_excl);
    cudaGetSymbolAddress((void**)&p_bsum,   g_bsum);
    cudaGetSymbolAddress((void**)&p_rowptr, g_rowptr);
    cudaGetSymbolAddress((void**)&p_fill,   g_fill);
    cudaGetSymbolAddress((void**)&p_eidx,   g_eidx);

    const int SMEM_BIG   = 73728;
    const int SMEM_SMALL = 55296;
    cudaFuncSetAttribute((const void*)gemm_f32a,
                         cudaFuncAttributeMaxDynamicSharedMemorySize, SMEM_BIG);
    cudaFuncSetAttribute((const void*)gemm_mma<256, 256, 128, 0>,
                         cudaFuncAttributeMaxDynamicSharedMemorySize, SMEM_BIG);
    cudaFuncSetAttribute((const void*)gemm_mma<256, 64, 64, 2>,
                         cudaFuncAttributeMaxDynamicSharedMemorySize, SMEM_SMALL);

    const int MB = (N_NODES + 127) / 128;   // 391
    const int EB = (N_EDGES + 255) / 256;   // 1250
    const int NB = (N_NODES + 255) / 256;   // 196

    // ---- all serial on stream 0; GEMMs at launch positions 4 and 6 ----

    // (1) w_in^T
    transpose_wt<<<dim3((IN_DIM * HID + 255) / 256, 1, 1), 256>>>(w_in, p_wt, IN_DIM, HID);
    // (2) conv1 W^T
    transpose_wt<<<dim3((HID * HID + 255) / 256, 1, R_REL), 256>>>(c1w, p_cwt, HID, HID);
    // (3) zero sq/sk
    zero_sqk<<<(R_REL * N_NODES + 255) / 256, 256>>>(p_sq, p_sk);
    // (4) h = relu(x @ w_in + b_in) -> fp16 (fused fp32 A conversion)
    gemm_f32a<<<dim3(MB, 2, 1), 256, SMEM_BIG>>>(x, p_wt, b_in, p_hh, N_NODES);
    // (5) out init
    out_init<<<(N_NODES * 2 + 255) / 256, 256>>>(out, b_cls);
    // (6) conv1 GEMM (fp16 xw + fused sq/sk)
    gemm_mma<256, 256, 128, 0><<<dim3(MB, 2, R_REL), 256, SMEM_BIG>>>(
        p_hh, p_cwt, nullptr, c1q, c1k, nullptr, p_xwh, p_sq, p_sk, N_NODES);

    // CSR build (needed before aggregate1 only)
    csr_zero   <<<NB, 256>>>(p_deg);
    csr_hist   <<<EB, 256>>>(dst, p_deg);
    csr_scan1  <<<NB, 256>>>(p_deg, p_excl, p_bsum);
    csr_scan2  <<<1,  256>>>(p_bsum);
    csr_scan3  <<<NB, 256>>>(p_excl, p_bsum, p_rowptr, p_fill);
    csr_scatter<<<EB, 256>>>(src, dst, edge_type, p_fill, p_eidx);

    // aggregate1 -> fp16 hh
    aggregate_kernel<<<N_NODES / 8, 256>>>(p_rowptr, p_eidx, p_sq, p_sk, p_xwh, c1b, p_hh);

    // conv2
    transpose_wt<<<dim3((HID * HID + 255) / 256, 1, R_REL), 256>>>(c2w, p_cwt, HID, HID);
    zero_sqk<<<(R_REL * N_NODES + 255) / 256, 256>>>(p_sq, p_sk);
    gemm_mma<256, 256, 128, 0><<<dim3(MB, 2, R_REL), 256, SMEM_BIG>>>(
        p_hh, p_cwt, nullptr, c2q, c2k, nullptr, p_xwh, p_sq, p_sk, N_NODES);
    aggregate_kernel<<<N_NODES / 8, 256>>>(p_rowptr, p_eidx, p_sq, p_sk, p_xwh, c2b, p_hh);

    // head: w_out^T, then out = (relu(h @ w_out + b_out)) @ w_cls + b_cls
    transpose_wt<<<dim3((HID * OUT_DIM + 255) / 256, 1, 1), 256>>>(w_out, p_wot, HID, OUT_DIM);
    gemm_mma<256, 64, 64, 2><<<dim3(MB, 1, 1), 256, SMEM_SMALL>>>(
        p_hh, p_wot, b_out, w_cls, nullptr, out, nullptr, nullptr, nullptr, N_NODES);
}